// round 5
// baseline (speedup 1.0000x reference)
#include <cuda_runtime.h>

// Problem constants (fixed by setup_inputs)
#define Bn   16
#define D    1024
#define H    16
#define HD   64
#define S    4096
#define SP   4097          // S + 1
#define SPAD 4112          // padded score row stride

// key pass tiling
#define KCH  128           // key rows per block
#define KNC  33            // ceil(4097/128)
#define KET  32            // e columns per tile
#define KSTR 36            // smem row stride: conflict-free LDS.128 at 32-row stride
#define KD   3             // pipeline depth
#define KNT  (D / KET)     // 32 tiles

// value pass tiling
#define VCH  128
#define VNC  33
#define VR   4             // rows per stage
#define VD   4             // pipeline depth
#define VNT  (VCH / VR)    // 32 stages

#define KSMEM_BYTES ((KD * KCH * KSTR + KD * H * KET) * 4)      // 61440
#define VSMEM_BYTES ((VD * VR * D + VD * H * VR) * 4)           // 66560

// Scratch (device globals; no allocation allowed)
__device__ float g_qw[Bn * H * D];
__device__ float g_scores[Bn * H * SPAD];
__device__ float g_avpart[(size_t)Bn * VNC * H * D];
__device__ float g_ctx[Bn * D];

// ---------------------------------------------------------------------------
// cp.async helpers
// ---------------------------------------------------------------------------
__device__ __forceinline__ void cp16(void* s, const void* g) {
    unsigned a = (unsigned)__cvta_generic_to_shared(s);
    asm volatile("cp.async.cg.shared.global [%0], [%1], 16;" :: "r"(a), "l"(g));
}
__device__ __forceinline__ void cp_commit() { asm volatile("cp.async.commit_group;"); }
template<int N> __device__ __forceinline__ void cp_wait() {
    asm volatile("cp.async.wait_group %0;" :: "n"(N));
}

// ---------------------------------------------------------------------------
// Kernel 1: q projection folded through wk. grid (H, B), 256 threads.
// ---------------------------------------------------------------------------
__global__ void __launch_bounds__(256) k_qproj(const float* __restrict__ query,
                                               const float* __restrict__ w_in,
                                               const float* __restrict__ b_in) {
    __shared__ float qs[D];
    __shared__ float qh[HD];
    const int h = blockIdx.x, b = blockIdx.y, tid = threadIdx.x;

    for (int i = tid; i < D; i += 256) qs[i] = query[b * D + i];
    __syncthreads();

    {
        int d = tid >> 2, sub = tid & 3;
        const float* wrow = w_in + (size_t)(h * HD + d) * D;
        float a = 0.f;
        #pragma unroll 8
        for (int e = sub; e < D; e += 4) a = fmaf(qs[e], wrow[e], a);
        a += __shfl_down_sync(0xffffffffu, a, 2, 4);
        a += __shfl_down_sync(0xffffffffu, a, 1, 4);
        if (sub == 0) qh[d] = (a + b_in[h * HD + d]) * 0.125f;
    }
    __syncthreads();

    for (int e = tid; e < D; e += 256) {
        float a = 0.f;
        #pragma unroll
        for (int d = 0; d < HD; d++)
            a = fmaf(qh[d], w_in[(size_t)(D + h * HD + d) * D + e], a);
        g_qw[(b * H + h) * D + e] = a;
    }
}

// ---------------------------------------------------------------------------
// Kernel 2: key pass — 3-deep cp.async pipeline, single barrier per tile.
//   copies past_key/key -> comb_key AND scores[b,h,k] = key_k · qw[b,h]
// grid (KNC, B), 256 threads. Warp: heads 4*(w&3).., k-half (w>>2).
// ---------------------------------------------------------------------------
__global__ void __launch_bounds__(256, 3) k_keys(const float* __restrict__ past_key,
                                                 const float* __restrict__ key,
                                                 float* __restrict__ comb_key) {
    extern __shared__ float sm[];
    float (*ks)[KCH][KSTR] = reinterpret_cast<float (*)[KCH][KSTR]>(sm);
    float (*qws)[H][KET]   = reinterpret_cast<float (*)[H][KET]>(sm + KD * KCH * KSTR);

    const int chunk = blockIdx.x, b = blockIdx.y, tid = threadIdx.x;
    const int k0 = chunk * KCH;
    const int w = tid >> 5, lane = tid & 31;
    const int hq = w & 3, kh = w >> 2;
    const int pr = tid >> 3, pc = (tid & 7) * 4;    // prefetch row base / col

    // per-thread global row sources (row = pr + 32*m); OOB rows alias the
    // always-valid current-token row (results discarded by guarded stores)
    const float* srcs[4];
    #pragma unroll
    for (int m = 0; m < 4; m++) {
        int kp = k0 + pr + 32 * m;
        srcs[m] = (kp < S) ? past_key + ((size_t)b * S + kp) * D + pc
                           : key + (size_t)b * D + pc;
    }
    const float* qsrc = g_qw + ((size_t)(b * H) + (tid >> 3)) * D + pc;

    #define KPREFETCH(T, BUF)                                               \
        do {                                                                \
            const int _et = (T) * KET;                                      \
            _Pragma("unroll")                                               \
            for (int m = 0; m < 4; m++)                                     \
                cp16(&ks[BUF][pr + 32 * m][pc], srcs[m] + _et);             \
            if (tid < 128) cp16(&qws[BUF][tid >> 3][pc], qsrc + _et);       \
        } while (0)

    KPREFETCH(0, 0); cp_commit();
    KPREFETCH(1, 1); cp_commit();

    float acc[4][2];
    #pragma unroll
    for (int a = 0; a < 4; a++) { acc[a][0] = 0.f; acc[a][1] = 0.f; }

    const int r0 = lane + 64 * kh;                   // rows r0 and r0+32

    for (int t = 0; t < KNT; t++) {
        cp_wait<KD - 2>();
        __syncthreads();
        if (t + KD - 1 < KNT) KPREFETCH(t + KD - 1, (t + KD - 1) % KD);
        cp_commit();

        const int buf = t % KD;
        const int et = t * KET;

        // copy tile -> comb_key
        #pragma unroll
        for (int m = 0; m < 4; m++) {
            int kp = k0 + pr + 32 * m;
            if (kp < SP)
                *(float4*)(comb_key + ((size_t)b * SP + kp) * D + et + pc)
                    = *(const float4*)&ks[buf][pr + 32 * m][pc];
        }
        // score accumulation: 4h x 2k per thread
        #pragma unroll
        for (int e4 = 0; e4 < KET / 4; e4++) {
            float4 kv0 = *(const float4*)&ks[buf][r0][e4 * 4];
            float4 kv1 = *(const float4*)&ks[buf][r0 + 32][e4 * 4];
            #pragma unroll
            for (int hh = 0; hh < 4; hh++) {
                float4 q4 = *(const float4*)&qws[buf][4 * hq + hh][e4 * 4];
                acc[hh][0] = fmaf(q4.x, kv0.x, acc[hh][0]);
                acc[hh][0] = fmaf(q4.y, kv0.y, acc[hh][0]);
                acc[hh][0] = fmaf(q4.z, kv0.z, acc[hh][0]);
                acc[hh][0] = fmaf(q4.w, kv0.w, acc[hh][0]);
                acc[hh][1] = fmaf(q4.x, kv1.x, acc[hh][1]);
                acc[hh][1] = fmaf(q4.y, kv1.y, acc[hh][1]);
                acc[hh][1] = fmaf(q4.z, kv1.z, acc[hh][1]);
                acc[hh][1] = fmaf(q4.w, kv1.w, acc[hh][1]);
            }
        }
    }

    #pragma unroll
    for (int hh = 0; hh < 4; hh++)
        #pragma unroll
        for (int jj = 0; jj < 2; jj++) {
            int k = k0 + r0 + 32 * jj;
            if (k < SP)
                g_scores[(size_t)(b * H + 4 * hq + hh) * SPAD + k] = acc[hh][jj];
        }
    #undef KPREFETCH
}

// ---------------------------------------------------------------------------
// Kernel 3: softmax over 4097 scores per (b,h); in place. grid 256, 256 thr.
// ---------------------------------------------------------------------------
__global__ void k_softmax() {
    __shared__ float red[32];
    __shared__ float bc;
    const int tid = threadIdx.x, lane = tid & 31, wid = tid >> 5;
    float* row = g_scores + (size_t)blockIdx.x * SPAD;

    float m = -1e30f;
    for (int i = tid; i < SP; i += 256) m = fmaxf(m, row[i]);
    #pragma unroll
    for (int o = 16; o; o >>= 1) m = fmaxf(m, __shfl_xor_sync(0xffffffffu, m, o));
    if (lane == 0) red[wid] = m;
    __syncthreads();
    if (tid == 0) {
        float v = red[0];
        for (int i = 1; i < 8; i++) v = fmaxf(v, red[i]);
        bc = v;
    }
    __syncthreads();
    const float M = bc;

    float s = 0.f;
    for (int i = tid; i < SP; i += 256) {
        float e = __expf(row[i] - M);
        row[i] = e;
        s += e;
    }
    #pragma unroll
    for (int o = 16; o; o >>= 1) s += __shfl_xor_sync(0xffffffffu, s, o);
    if (lane == 0) red[wid] = s;
    __syncthreads();
    if (tid == 0) {
        float v = 0.f;
        for (int i = 0; i < 8; i++) v += red[i];
        bc = 1.f / v;
    }
    __syncthreads();
    const float inv = bc;
    for (int i = tid; i < SP; i += 256) row[i] *= inv;
}

// ---------------------------------------------------------------------------
// Kernel 4: value pass — 4-deep cp.async pipeline, single barrier per stage.
//   copies past_value/value -> comb_value AND accumulates
//   avpart[b,chunk,h,e] = sum_k attn[b,h,k] * v[b,k,e]
// grid (VNC, B), 256 threads. Thread: 4 heads x 16 e (float4 x 4).
// ---------------------------------------------------------------------------
__global__ void __launch_bounds__(256, 3) k_values(const float* __restrict__ past_value,
                                                   const float* __restrict__ value,
                                                   float* __restrict__ comb_value) {
    extern __shared__ float sm[];
    float (*vs)[VR][D] = reinterpret_cast<float (*)[VR][D]>(sm);
    float (*as)[H][VR] = reinterpret_cast<float (*)[H][VR]>(sm + VD * VR * D);

    const int chunk = blockIdx.x, b = blockIdx.y, tid = threadIdx.x;
    const int k0 = chunk * VCH;
    const int hq = tid >> 6, eq = tid & 63;

    #define VPREFETCH(ST, BUF)                                                    \
        do {                                                                      \
            _Pragma("unroll")                                                     \
            for (int r = 0; r < VR; r++) {                                        \
                int kp = k0 + (ST) * VR + r;                                      \
                const float* src = (kp < S)                                       \
                    ? past_value + ((size_t)b * S + kp) * D                       \
                    : value + (size_t)b * D;                                      \
                cp16(&vs[BUF][r][tid * 4], src + tid * 4);                        \
            }                                                                     \
            if (tid < 16)                                                         \
                cp16(&as[BUF][tid][0],                                            \
                     g_scores + (size_t)(b * H + tid) * SPAD + k0 + (ST) * VR);   \
        } while (0)

    VPREFETCH(0, 0); cp_commit();
    VPREFETCH(1, 1); cp_commit();
    VPREFETCH(2, 2); cp_commit();

    float4 acc[4][4];
    #pragma unroll
    for (int a = 0; a < 4; a++)
        #pragma unroll
        for (int j = 0; j < 4; j++) acc[a][j] = make_float4(0.f, 0.f, 0.f, 0.f);

    for (int st = 0; st < VNT; st++) {
        cp_wait<VD - 2>();
        __syncthreads();
        if (st + VD - 1 < VNT) VPREFETCH(st + VD - 1, (st + VD - 1) & (VD - 1));
        cp_commit();

        const int buf = st & (VD - 1);

        // copy stage -> comb_value
        #pragma unroll
        for (int r = 0; r < VR; r++) {
            int kp = k0 + st * VR + r;
            if (kp < SP)
                *(float4*)(comb_value + ((size_t)b * SP + kp) * D + tid * 4)
                    = *(const float4*)&vs[buf][r][tid * 4];
        }
        // accumulate
        #pragma unroll
        for (int r = 0; r < VR; r++) {
            const int kp = k0 + st * VR + r;
            const bool ok = kp < SP;
            float w0 = ok ? as[buf][4 * hq + 0][r] : 0.f;
            float w1 = ok ? as[buf][4 * hq + 1][r] : 0.f;
            float w2 = ok ? as[buf][4 * hq + 2][r] : 0.f;
            float w3 = ok ? as[buf][4 * hq + 3][r] : 0.f;
            #pragma unroll
            for (int j = 0; j < 4; j++) {
                float4 v4 = *(const float4*)&vs[buf][r][eq * 4 + 256 * j];
                acc[0][j].x = fmaf(w0, v4.x, acc[0][j].x);
                acc[0][j].y = fmaf(w0, v4.y, acc[0][j].y);
                acc[0][j].z = fmaf(w0, v4.z, acc[0][j].z);
                acc[0][j].w = fmaf(w0, v4.w, acc[0][j].w);
                acc[1][j].x = fmaf(w1, v4.x, acc[1][j].x);
                acc[1][j].y = fmaf(w1, v4.y, acc[1][j].y);
                acc[1][j].z = fmaf(w1, v4.z, acc[1][j].z);
                acc[1][j].w = fmaf(w1, v4.w, acc[1][j].w);
                acc[2][j].x = fmaf(w2, v4.x, acc[2][j].x);
                acc[2][j].y = fmaf(w2, v4.y, acc[2][j].y);
                acc[2][j].z = fmaf(w2, v4.z, acc[2][j].z);
                acc[2][j].w = fmaf(w2, v4.w, acc[2][j].w);
                acc[3][j].x = fmaf(w3, v4.x, acc[3][j].x);
                acc[3][j].y = fmaf(w3, v4.y, acc[3][j].y);
                acc[3][j].z = fmaf(w3, v4.z, acc[3][j].z);
                acc[3][j].w = fmaf(w3, v4.w, acc[3][j].w);
            }
        }
    }

    #pragma unroll
    for (int hh = 0; hh < 4; hh++)
        #pragma unroll
        for (int j = 0; j < 4; j++)
            *(float4*)&g_avpart[(((size_t)b * VNC + chunk) * H + 4 * hq + hh) * D
                                + eq * 4 + 256 * j] = acc[hh][j];
    #undef VPREFETCH
}

// ---------------------------------------------------------------------------
// Kernel 5: fold chunk partials + ctx = av @ wv^T + bv.  grid (H, B), 256 thr.
// ---------------------------------------------------------------------------
__global__ void __launch_bounds__(256) k_fold(const float* __restrict__ w_in,
                                              const float* __restrict__ b_in) {
    __shared__ float avs[D];
    const int h = blockIdx.x, b = blockIdx.y, tid = threadIdx.x;

    for (int e = tid; e < D; e += 256) {
        float s = 0.f;
        #pragma unroll
        for (int c = 0; c < VNC; c++)
            s += g_avpart[(((size_t)b * VNC + c) * H + h) * D + e];
        avs[e] = s;
    }
    __syncthreads();

    int d = tid >> 2, sub = tid & 3;
    const float* wrow = w_in + (size_t)(2 * D + h * HD + d) * D;
    float a = 0.f;
    #pragma unroll 8
    for (int e = sub; e < D; e += 4) a = fmaf(avs[e], wrow[e], a);
    a += __shfl_down_sync(0xffffffffu, a, 2, 4);
    a += __shfl_down_sync(0xffffffffu, a, 1, 4);
    if (sub == 0) g_ctx[b * D + h * HD + d] = a + b_in[2 * D + h * HD + d];
}

// ---------------------------------------------------------------------------
// Kernel 6: out = ctx @ w_out^T + b_out.  grid (16, B), 256 thr.
// ---------------------------------------------------------------------------
__global__ void __launch_bounds__(256) k_out(const float* __restrict__ w_out,
                                             const float* __restrict__ b_out,
                                             float* __restrict__ out) {
    __shared__ float cs[D];
    const int og = blockIdx.x, b = blockIdx.y, tid = threadIdx.x;

    for (int i = tid; i < D; i += 256) cs[i] = g_ctx[b * D + i];
    __syncthreads();

    int o = og * 64 + (tid >> 2), sub = tid & 3;
    const float* wrow = w_out + (size_t)o * D;
    float a = 0.f;
    #pragma unroll 8
    for (int dt = sub; dt < D; dt += 4) a = fmaf(cs[dt], wrow[dt], a);
    a += __shfl_down_sync(0xffffffffu, a, 2, 4);
    a += __shfl_down_sync(0xffffffffu, a, 1, 4);
    if (sub == 0) out[(size_t)b * D + o] = a + b_out[o];
}

// ---------------------------------------------------------------------------
extern "C" void kernel_launch(void* const* d_in, const int* in_sizes, int n_in,
                              void* d_out, int out_size) {
    (void)in_sizes; (void)n_in; (void)out_size;
    const float* query      = (const float*)d_in[0];
    const float* key        = (const float*)d_in[1];
    const float* value      = (const float*)d_in[2];
    const float* past_key   = (const float*)d_in[3];
    const float* past_value = (const float*)d_in[4];
    const float* w_in       = (const float*)d_in[5];
    const float* b_in       = (const float*)d_in[6];
    const float* w_out      = (const float*)d_in[7];
    const float* b_out      = (const float*)d_in[8];

    float* out        = (float*)d_out;                      // [16,1,1024]
    float* comb_key   = out + (size_t)Bn * D;               // [16,4097,1024]
    float* comb_value = comb_key + (size_t)Bn * SP * D;     // [16,4097,1024]

    cudaFuncSetAttribute(k_keys,   cudaFuncAttributeMaxDynamicSharedMemorySize, KSMEM_BYTES);
    cudaFuncSetAttribute(k_values, cudaFuncAttributeMaxDynamicSharedMemorySize, VSMEM_BYTES);

    k_qproj  <<<dim3(H, Bn),   256>>>(query, w_in, b_in);
    k_keys   <<<dim3(KNC, Bn), 256, KSMEM_BYTES>>>(past_key, key, comb_key);
    k_softmax<<<Bn * H,        256>>>();
    k_values <<<dim3(VNC, Bn), 256, VSMEM_BYTES>>>(past_value, value, comb_value);
    k_fold   <<<dim3(H, Bn),   256>>>(w_in, b_in);
    k_out    <<<dim3(16, Bn),  256>>>(w_out, b_out, out);
}

// round 6
// speedup vs baseline: 1.3589x; 1.3589x over previous
#include <cuda_runtime.h>

// Problem constants (fixed by setup_inputs)
#define Bn   16
#define D    1024
#define H    16
#define HD   64
#define S    4096
#define SP   4097          // S + 1
#define SPAD 4112          // padded score row stride

// key pass tiling (unchanged from R4 — measured neutral)
#define KCH  128
#define KNC  33
#define KET  32
#define KSTR 36
#define KD   3
#define KNT  (D / KET)
#define KSMEM_BYTES ((KD * KCH * KSTR + KD * H * KET) * 4)

// value pass tiling (register-direct)
#define VCH  128
#define VNC  33
#define PF   8             // rolling register prefetch depth

// Scratch (device globals; no allocation allowed)
__device__ float g_qw[Bn * H * D];
__device__ float g_scores[Bn * H * SPAD];
__device__ float g_avpart[(size_t)Bn * VNC * H * D];
__device__ float g_ctx[Bn * D];

// ---------------------------------------------------------------------------
// cp.async helpers (key pass only)
// ---------------------------------------------------------------------------
__device__ __forceinline__ void cp16(void* s, const void* g) {
    unsigned a = (unsigned)__cvta_generic_to_shared(s);
    asm volatile("cp.async.cg.shared.global [%0], [%1], 16;" :: "r"(a), "l"(g));
}
__device__ __forceinline__ void cp_commit() { asm volatile("cp.async.commit_group;"); }
template<int N> __device__ __forceinline__ void cp_wait() {
    asm volatile("cp.async.wait_group %0;" :: "n"(N));
}

// ---------------------------------------------------------------------------
// Kernel 1: q projection folded through wk. grid (H, B), 256 threads.
// ---------------------------------------------------------------------------
__global__ void __launch_bounds__(256) k_qproj(const float* __restrict__ query,
                                               const float* __restrict__ w_in,
                                               const float* __restrict__ b_in) {
    __shared__ float qs[D];
    __shared__ float qh[HD];
    const int h = blockIdx.x, b = blockIdx.y, tid = threadIdx.x;

    for (int i = tid; i < D; i += 256) qs[i] = query[b * D + i];
    __syncthreads();

    {
        int d = tid >> 2, sub = tid & 3;
        const float* wrow = w_in + (size_t)(h * HD + d) * D;
        float a = 0.f;
        #pragma unroll 8
        for (int e = sub; e < D; e += 4) a = fmaf(qs[e], wrow[e], a);
        a += __shfl_down_sync(0xffffffffu, a, 2, 4);
        a += __shfl_down_sync(0xffffffffu, a, 1, 4);
        if (sub == 0) qh[d] = (a + b_in[h * HD + d]) * 0.125f;
    }
    __syncthreads();

    for (int e = tid; e < D; e += 256) {
        float a = 0.f;
        #pragma unroll
        for (int d = 0; d < HD; d++)
            a = fmaf(qh[d], w_in[(size_t)(D + h * HD + d) * D + e], a);
        g_qw[(b * H + h) * D + e] = a;
    }
}

// ---------------------------------------------------------------------------
// Kernel 2: key pass — 3-deep cp.async pipeline (unchanged from R4).
// grid (KNC, B), 256 threads.
// ---------------------------------------------------------------------------
__global__ void __launch_bounds__(256, 3) k_keys(const float* __restrict__ past_key,
                                                 const float* __restrict__ key,
                                                 float* __restrict__ comb_key) {
    extern __shared__ float sm[];
    float (*ks)[KCH][KSTR] = reinterpret_cast<float (*)[KCH][KSTR]>(sm);
    float (*qws)[H][KET]   = reinterpret_cast<float (*)[H][KET]>(sm + KD * KCH * KSTR);

    const int chunk = blockIdx.x, b = blockIdx.y, tid = threadIdx.x;
    const int k0 = chunk * KCH;
    const int w = tid >> 5, lane = tid & 31;
    const int hq = w & 3, kh = w >> 2;
    const int pr = tid >> 3, pc = (tid & 7) * 4;

    const float* srcs[4];
    #pragma unroll
    for (int m = 0; m < 4; m++) {
        int kp = k0 + pr + 32 * m;
        srcs[m] = (kp < S) ? past_key + ((size_t)b * S + kp) * D + pc
                           : key + (size_t)b * D + pc;
    }
    const float* qsrc = g_qw + ((size_t)(b * H) + (tid >> 3)) * D + pc;

    #define KPREFETCH(T, BUF)                                               \
        do {                                                                \
            const int _et = (T) * KET;                                      \
            _Pragma("unroll")                                               \
            for (int m = 0; m < 4; m++)                                     \
                cp16(&ks[BUF][pr + 32 * m][pc], srcs[m] + _et);             \
            if (tid < 128) cp16(&qws[BUF][tid >> 3][pc], qsrc + _et);       \
        } while (0)

    KPREFETCH(0, 0); cp_commit();
    KPREFETCH(1, 1); cp_commit();

    float acc[4][2];
    #pragma unroll
    for (int a = 0; a < 4; a++) { acc[a][0] = 0.f; acc[a][1] = 0.f; }

    const int r0 = lane + 64 * kh;

    for (int t = 0; t < KNT; t++) {
        cp_wait<KD - 2>();
        __syncthreads();
        if (t + KD - 1 < KNT) KPREFETCH(t + KD - 1, (t + KD - 1) % KD);
        cp_commit();

        const int buf = t % KD;
        const int et = t * KET;

        #pragma unroll
        for (int m = 0; m < 4; m++) {
            int kp = k0 + pr + 32 * m;
            if (kp < SP)
                *(float4*)(comb_key + ((size_t)b * SP + kp) * D + et + pc)
                    = *(const float4*)&ks[buf][pr + 32 * m][pc];
        }
        #pragma unroll
        for (int e4 = 0; e4 < KET / 4; e4++) {
            float4 kv0 = *(const float4*)&ks[buf][r0][e4 * 4];
            float4 kv1 = *(const float4*)&ks[buf][r0 + 32][e4 * 4];
            #pragma unroll
            for (int hh = 0; hh < 4; hh++) {
                float4 q4 = *(const float4*)&qws[buf][4 * hq + hh][e4 * 4];
                acc[hh][0] = fmaf(q4.x, kv0.x, acc[hh][0]);
                acc[hh][0] = fmaf(q4.y, kv0.y, acc[hh][0]);
                acc[hh][0] = fmaf(q4.z, kv0.z, acc[hh][0]);
                acc[hh][0] = fmaf(q4.w, kv0.w, acc[hh][0]);
                acc[hh][1] = fmaf(q4.x, kv1.x, acc[hh][1]);
                acc[hh][1] = fmaf(q4.y, kv1.y, acc[hh][1]);
                acc[hh][1] = fmaf(q4.z, kv1.z, acc[hh][1]);
                acc[hh][1] = fmaf(q4.w, kv1.w, acc[hh][1]);
            }
        }
    }

    #pragma unroll
    for (int hh = 0; hh < 4; hh++)
        #pragma unroll
        for (int jj = 0; jj < 2; jj++) {
            int k = k0 + r0 + 32 * jj;
            if (k < SP)
                g_scores[(size_t)(b * H + 4 * hq + hh) * SPAD + k] = acc[hh][jj];
        }
    #undef KPREFETCH
}

// ---------------------------------------------------------------------------
// Kernel 3: softmax over 4097 scores per (b,h); in place. grid 256, 256 thr.
// ---------------------------------------------------------------------------
__global__ void k_softmax() {
    __shared__ float red[32];
    __shared__ float bc;
    const int tid = threadIdx.x, lane = tid & 31, wid = tid >> 5;
    float* row = g_scores + (size_t)blockIdx.x * SPAD;

    float m = -1e30f;
    for (int i = tid; i < SP; i += 256) m = fmaxf(m, row[i]);
    #pragma unroll
    for (int o = 16; o; o >>= 1) m = fmaxf(m, __shfl_xor_sync(0xffffffffu, m, o));
    if (lane == 0) red[wid] = m;
    __syncthreads();
    if (tid == 0) {
        float v = red[0];
        for (int i = 1; i < 8; i++) v = fmaxf(v, red[i]);
        bc = v;
    }
    __syncthreads();
    const float M = bc;

    float s = 0.f;
    for (int i = tid; i < SP; i += 256) {
        float e = __expf(row[i] - M);
        row[i] = e;
        s += e;
    }
    #pragma unroll
    for (int o = 16; o; o >>= 1) s += __shfl_xor_sync(0xffffffffu, s, o);
    if (lane == 0) red[wid] = s;
    __syncthreads();
    if (tid == 0) {
        float v = 0.f;
        for (int i = 0; i < 8; i++) v += red[i];
        bc = 1.f / v;
    }
    __syncthreads();
    const float inv = bc;
    for (int i = tid; i < SP; i += 256) row[i] *= inv;
}

// ---------------------------------------------------------------------------
// Kernel 4: value pass — register-direct, all 16 heads per thread.
//   Thread owns e-column tid*4..tid*4+3. Per k-row: LDG.128 (direct),
//   STG.128 -> comb_value, 4 broadcast LDS.128 (attn), 64 FMA.
//   8-deep rolling register prefetch; no barriers in the k loop.
// grid (VNC, B), 256 threads.
// ---------------------------------------------------------------------------
__global__ void __launch_bounds__(256, 2) k_values(const float* __restrict__ past_value,
                                                   const float* __restrict__ value,
                                                   float* __restrict__ comb_value) {
    __shared__ float as[VCH][20];          // [k][h], stride 20: aligned + conflict-free
    const int chunk = blockIdx.x, b = blockIdx.y, tid = threadIdx.x;
    const int k0 = chunk * VCH;

    // stage attn weights once: as[k][h], zero for OOB k
    for (int i = tid; i < VCH * H; i += 256) {
        int h = i >> 7, k = i & (VCH - 1);
        as[k][h] = (k0 + k < SP) ? g_scores[(size_t)(b * H + h) * SPAD + k0 + k] : 0.f;
    }
    __syncthreads();

    const float* vrow_cur = value + (size_t)b * D + tid * 4;   // current-token row
    const float* pv_base  = past_value + ((size_t)b * S) * D + tid * 4;

    float4 acc[16];
    #pragma unroll
    for (int h = 0; h < 16; h++) acc[h] = make_float4(0.f, 0.f, 0.f, 0.f);

    float4 vbuf[PF];
    #pragma unroll
    for (int p = 0; p < PF; p++) {
        int kp = k0 + p;
        vbuf[p] = *(const float4*)((kp < S) ? pv_base + (size_t)kp * D : vrow_cur);
    }

    for (int kb = 0; kb < VCH; kb += PF) {
        #pragma unroll
        for (int p = 0; p < PF; p++) {
            const int k = kb + p;
            const float4 v = vbuf[p];

            // prefetch row k + PF
            if (kb + PF < VCH) {
                int kn = k0 + k + PF;
                vbuf[p] = *(const float4*)((kn < S) ? pv_base + (size_t)kn * D : vrow_cur);
            }
            // copy to comb_value
            int kp = k0 + k;
            if (kp < SP)
                *(float4*)(comb_value + ((size_t)b * SP + kp) * D + tid * 4) = v;

            // accumulate all 16 heads
            #pragma unroll
            for (int h4 = 0; h4 < 4; h4++) {
                float4 w = *(const float4*)&as[k][h4 * 4];
                acc[h4 * 4 + 0].x = fmaf(w.x, v.x, acc[h4 * 4 + 0].x);
                acc[h4 * 4 + 0].y = fmaf(w.x, v.y, acc[h4 * 4 + 0].y);
                acc[h4 * 4 + 0].z = fmaf(w.x, v.z, acc[h4 * 4 + 0].z);
                acc[h4 * 4 + 0].w = fmaf(w.x, v.w, acc[h4 * 4 + 0].w);
                acc[h4 * 4 + 1].x = fmaf(w.y, v.x, acc[h4 * 4 + 1].x);
                acc[h4 * 4 + 1].y = fmaf(w.y, v.y, acc[h4 * 4 + 1].y);
                acc[h4 * 4 + 1].z = fmaf(w.y, v.z, acc[h4 * 4 + 1].z);
                acc[h4 * 4 + 1].w = fmaf(w.y, v.w, acc[h4 * 4 + 1].w);
                acc[h4 * 4 + 2].x = fmaf(w.z, v.x, acc[h4 * 4 + 2].x);
                acc[h4 * 4 + 2].y = fmaf(w.z, v.y, acc[h4 * 4 + 2].y);
                acc[h4 * 4 + 2].z = fmaf(w.z, v.z, acc[h4 * 4 + 2].z);
                acc[h4 * 4 + 2].w = fmaf(w.z, v.w, acc[h4 * 4 + 2].w);
                acc[h4 * 4 + 3].x = fmaf(w.w, v.x, acc[h4 * 4 + 3].x);
                acc[h4 * 4 + 3].y = fmaf(w.w, v.y, acc[h4 * 4 + 3].y);
                acc[h4 * 4 + 3].z = fmaf(w.w, v.z, acc[h4 * 4 + 3].z);
                acc[h4 * 4 + 3].w = fmaf(w.w, v.w, acc[h4 * 4 + 3].w);
            }
        }
    }

    #pragma unroll
    for (int h = 0; h < 16; h++)
        *(float4*)&g_avpart[(((size_t)b * VNC + chunk) * H + h) * D + tid * 4] = acc[h];
}

// ---------------------------------------------------------------------------
// Kernel 5: fold chunk partials + ctx = av @ wv^T + bv.  grid (H, B), 256 thr.
// ---------------------------------------------------------------------------
__global__ void __launch_bounds__(256) k_fold(const float* __restrict__ w_in,
                                              const float* __restrict__ b_in) {
    __shared__ float avs[D];
    const int h = blockIdx.x, b = blockIdx.y, tid = threadIdx.x;

    for (int e = tid; e < D; e += 256) {
        float s = 0.f;
        #pragma unroll
        for (int c = 0; c < VNC; c++)
            s += g_avpart[(((size_t)b * VNC + c) * H + h) * D + e];
        avs[e] = s;
    }
    __syncthreads();

    int d = tid >> 2, sub = tid & 3;
    const float* wrow = w_in + (size_t)(2 * D + h * HD + d) * D;
    float a = 0.f;
    #pragma unroll 8
    for (int e = sub; e < D; e += 4) a = fmaf(avs[e], wrow[e], a);
    a += __shfl_down_sync(0xffffffffu, a, 2, 4);
    a += __shfl_down_sync(0xffffffffu, a, 1, 4);
    if (sub == 0) g_ctx[b * D + h * HD + d] = a + b_in[2 * D + h * HD + d];
}

// ---------------------------------------------------------------------------
// Kernel 6: out = ctx @ w_out^T + b_out.  grid (16, B), 256 thr.
// ---------------------------------------------------------------------------
__global__ void __launch_bounds__(256) k_out(const float* __restrict__ w_out,
                                             const float* __restrict__ b_out,
                                             float* __restrict__ out) {
    __shared__ float cs[D];
    const int og = blockIdx.x, b = blockIdx.y, tid = threadIdx.x;

    for (int i = tid; i < D; i += 256) cs[i] = g_ctx[b * D + i];
    __syncthreads();

    int o = og * 64 + (tid >> 2), sub = tid & 3;
    const float* wrow = w_out + (size_t)o * D;
    float a = 0.f;
    #pragma unroll 8
    for (int dt = sub; dt < D; dt += 4) a = fmaf(cs[dt], wrow[dt], a);
    a += __shfl_down_sync(0xffffffffu, a, 2, 4);
    a += __shfl_down_sync(0xffffffffu, a, 1, 4);
    if (sub == 0) out[(size_t)b * D + o] = a + b_out[o];
}

// ---------------------------------------------------------------------------
extern "C" void kernel_launch(void* const* d_in, const int* in_sizes, int n_in,
                              void* d_out, int out_size) {
    (void)in_sizes; (void)n_in; (void)out_size;
    const float* query      = (const float*)d_in[0];
    const float* key        = (const float*)d_in[1];
    const float* value      = (const float*)d_in[2];
    const float* past_key   = (const float*)d_in[3];
    const float* past_value = (const float*)d_in[4];
    const float* w_in       = (const float*)d_in[5];
    const float* b_in       = (const float*)d_in[6];
    const float* w_out      = (const float*)d_in[7];
    const float* b_out      = (const float*)d_in[8];

    float* out        = (float*)d_out;                      // [16,1,1024]
    float* comb_key   = out + (size_t)Bn * D;               // [16,4097,1024]
    float* comb_value = comb_key + (size_t)Bn * SP * D;     // [16,4097,1024]

    cudaFuncSetAttribute(k_keys, cudaFuncAttributeMaxDynamicSharedMemorySize, KSMEM_BYTES);

    k_qproj  <<<dim3(H, Bn),   256>>>(query, w_in, b_in);
    k_keys   <<<dim3(KNC, Bn), 256, KSMEM_BYTES>>>(past_key, key, comb_key);
    k_softmax<<<Bn * H,        256>>>();
    k_values <<<dim3(VNC, Bn), 256>>>(past_value, value, comb_value);
    k_fold   <<<dim3(H, Bn),   256>>>(w_in, b_in);
    k_out    <<<dim3(16, Bn),  256>>>(w_out, b_out, out);
}